// round 9
// baseline (speedup 1.0000x reference)
#include <cuda_runtime.h>
#include <cuda_fp16.h>
#include <math.h>

// ---------------- device scratch (static: allocations are forbidden) -------
// Conv A operand, fp16x2 fragment-major for mma.m16n8k16:
// [par(8)][kc(8)][cpi(4)][mt(6)][lane(32)][r(4)]  (each u32 = fp16x2)
__device__ unsigned g_A16[8 * 8 * 3072];
// Combine A operand: [k2(6)][mt(2)][lane(32)][r(4)] fp16x2
__device__ unsigned g_A2[1536];
__device__ float g_bias1[32];
__device__ float g_bias2[32];

// ---------------- helpers ----------------------------------------------------
__device__ __forceinline__ void mma_f16(float* d, const unsigned* a,
                                        unsigned b0, unsigned b1) {
    asm volatile(
        "mma.sync.aligned.m16n8k16.row.col.f32.f16.f16.f32 "
        "{%0,%1,%2,%3}, {%4,%5,%6,%7}, {%8,%9}, {%0,%1,%2,%3};"
        : "+f"(d[0]), "+f"(d[1]), "+f"(d[2]), "+f"(d[3])
        : "r"(a[0]), "r"(a[1]), "r"(a[2]), "r"(a[3]), "r"(b0), "r"(b1));
}

// per-axis trilinear->original-grid collapse weights (fp32: exact small
// rationals; error ~1e-7 invisible under fp16 quantization)
__device__ __forceinline__ float hvalf(int q, int k, int e, float a) {
    if (q == 0) {
        if (k == 0) return e ? a : (1.0f - a);
        return e ? 1.0f : 0.0f;
    } else {
        if (k == 2) return e ? (1.0f - a) : a;
        return e ? 0.0f : 1.0f;
    }
}

// ---------------- merged setup kernel ----------------------------------------
// grid (64 c, 8 par), block 192 = 6 mt x 32 lanes.
__global__ void setup_all(const float* __restrict__ W,
                          const float* __restrict__ g1, const float* __restrict__ v1,
                          const float* __restrict__ b_def,
                          const float* __restrict__ b1, const float* __restrict__ m1,
                          const float* __restrict__ wcm, const float* __restrict__ bcm,
                          const float* __restrict__ g2, const float* __restrict__ b2,
                          const float* __restrict__ m2, const float* __restrict__ v2) {
    __shared__ float ws[32 * 27];
    int c = blockIdx.x, par = blockIdx.y;
    int tid = threadIdx.x;
    for (int idx = tid; idx < 32 * 27; idx += 192) {
        int co = idx / 27, kk = idx - co * 27;
        ws[idx] = W[co * 1728 + c * 27 + kk];
    }
    __syncthreads();

    int mt = tid >> 5, lane = tid & 31;
    int g = lane >> 2, t4 = lane & 3;
    int qz = (par >> 2) & 1, qy = (par >> 1) & 1, qx = par & 1;

#pragma unroll
    for (int rowbit = 0; rowbit < 2; rowbit++) {
        int m = mt * 16 + g + 8 * rowbit;
        int br = m >> 5, co = m & 31;
        float a = (br == 0) ? 0.0f : (br == 1 ? 0.4f : 0.7f);
        float s1 = g1[co] * rsqrtf(v1[co] + 1e-5f);
        __half hh[2];
#pragma unroll
        for (int h = 0; h < 2; h++) {
            int tap = 2 * t4 + h;
            int ez = (tap >> 2) & 1, ey = (tap >> 1) & 1, ex = tap & 1;
            float hz[3], hy[3], hx[3];
#pragma unroll
            for (int k = 0; k < 3; k++) {
                hz[k] = hvalf(qz, k, ez, a);
                hy[k] = hvalf(qy, k, ey, a);
                hx[k] = hvalf(qx, k, ex, a);
            }
            float sum = 0.f;
#pragma unroll
            for (int kz = 0; kz < 3; kz++)
#pragma unroll
                for (int ky = 0; ky < 3; ky++)
#pragma unroll
                    for (int kx = 0; kx < 3; kx++)
                        sum += ws[co * 27 + kz * 9 + ky * 3 + kx] *
                               (hz[kz] * hy[ky] * hx[kx]);
            hh[h] = __float2half(sum * s1);
        }
        int r = 2 * (c & 1) + rowbit;
        int idx = ((((par * 8 + (c >> 3)) * 4 + ((c >> 1) & 3)) * 6 + mt) * 32 + lane) * 4 + r;
        __half2 hv = __halves2half2(hh[0], hh[1]);
        g_A16[idx] = *(unsigned*)&hv;
    }

    if (blockIdx.x == 0 && blockIdx.y == 0) {
        if (tid < 32) {
            float s1 = g1[tid] * rsqrtf(v1[tid] + 1e-5f);
            g_bias1[tid] = b_def[tid] * s1 + b1[tid] - m1[tid] * s1;
            float s2 = g2[tid] * rsqrtf(v2[tid] + 1e-5f);
            g_bias2[tid] = bcm[tid] * s2 + b2[tid] - m2[tid] * s2;
        }
        for (int idx = tid; idx < 1536; idx += 192) {
            int r = idx & 3, ln = (idx >> 2) & 31, mt2 = (idx >> 7) & 1, k2 = idx >> 8;
            int gg = ln >> 2, tt = ln & 3;
            int m = mt2 * 16 + gg + 8 * (r & 1);
            float s2 = g2[m] * rsqrtf(v2[m] + 1e-5f);
            int ch0 = k2 * 16 + 8 * (r >> 1) + 2 * tt;
            __half2 hv = __halves2half2(__float2half(wcm[m * 96 + ch0] * s2),
                                        __float2half(wcm[m * 96 + ch0 + 1] * s2));
            g_A2[idx] = *(unsigned*)&hv;
        }
    }
}

// ---------------- main fused kernel ------------------------------------------
// block 256 thr = 8 warps; tile = 8(x) x 8(y) x 4(z) orig coords = 256 voxels,
// one parity class. x tile held 32 channels at a time (2 phases) as overlapping
// fp16x2 pairs in smem. A fragments are LDG'd straight from the L2-hot table:
// NO smem staging, NO barriers in the kc loop — warps run fully independent.
#define XT_U32 12960            // 32c * 405 positions (fp16x2 pairs)
#define SA2_U32 1536
#define SMEM_BYTES ((XT_U32 + SA2_U32 + 64) * 4)

__global__ void __launch_bounds__(256, 2)
conv_main(const float* __restrict__ x, float* __restrict__ out) {
    extern __shared__ unsigned smu[];
    unsigned* xt = smu;                         // also R_t after conv
    unsigned* sA2 = smu + XT_U32;
    float* b1s = (float*)(sA2 + SA2_U32);
    float* b2s = b1s + 32;

    const int tid = threadIdx.x;
    const int w = tid >> 5, lane = tid & 31;
    const int g = lane >> 2, t4 = lane & 3;

    const int par = blockIdx.z >> 3;
    const int pzt = blockIdx.z & 7;
    const int qz = (par >> 2) & 1, qy = (par >> 1) & 1, qx = par & 1;
    const int Px0 = blockIdx.x * 8, Py0 = blockIdx.y * 8, Pz0 = pzt * 4;
    const int ox = Px0 - 1 + qx, oy = Py0 - 1 + qy, oz = Pz0 - 1 + qz;

    const unsigned* gA = g_A16 + par * 24576 + lane * 4;   // per-lane base

    // ---- hoisted loader coords: 2 fixed tile positions per thread ----
    const int p0 = tid;                       // 0..255 (<405 always)
    int z0 = p0 / 81, r0 = p0 - z0 * 81, y0 = r0 / 9, x0 = r0 - y0 * 9;
    int gz0 = oz + z0, gy0 = oy + y0, gx0 = ox + x0;
    const bool ok0 = ((unsigned)gz0 < 32u) && ((unsigned)gy0 < 32u) &&
                     ((unsigned)gx0 < 32u);
    const int off0 = (gz0 * 32 + gy0) * 32 + gx0;

    const int p1 = tid + 256;
    const bool has1 = p1 < 405;
    int z1 = p1 / 81, r1 = p1 - z1 * 81, y1 = r1 / 9, x1 = r1 - y1 * 9;
    int gz1 = oz + z1, gy1 = oy + y1, gx1 = ox + x1;
    const bool ok1 = has1 && ((unsigned)gz1 < 32u) && ((unsigned)gy1 < 32u) &&
                     ((unsigned)gx1 < 32u);
    const int off1 = (gz1 * 32 + gy1) * 32 + gx1;

    // x tile as overlapping fp16 pairs: pair idx holds halves (pos, pos+1)
    auto load_half = [&](int phase) {
        const float* xb = x + phase * 32 * 32768;
        __half* hp = (__half*)xt;
#pragma unroll 8
        for (int c = 0; c < 32; c++) {
            float v0 = ok0 ? __ldg(xb + c * 32768 + off0) : 0.f;
            __half h0 = __float2half(v0);
            int i0 = c * 405 + p0;
            hp[2 * i0] = h0;
            if (p0) hp[2 * i0 - 1] = h0;
            if (has1) {
                float v1v = ok1 ? __ldg(xb + c * 32768 + off1) : 0.f;
                __half h1 = __float2half(v1v);
                int i1 = c * 405 + p1;
                hp[2 * i1] = h1;
                hp[2 * i1 - 1] = h1;
            }
        }
    };

    load_half(0);
    for (int i = tid; i < SA2_U32; i += 256) sA2[i] = g_A2[i];
    if (tid < 32) { b1s[tid] = g_bias1[tid]; b2s[tid] = g_bias2[tid]; }
    __syncthreads();

    // ---- per-lane B gather offsets ----
    int boff[4];
#pragma unroll
    for (int nt = 0; nt < 4; nt++) {
        int vox = w * 32 + nt * 8 + g;
        boff[nt] = (vox >> 6) * 81 + ((vox >> 3) & 7) * 9 + (vox & 7);
    }
    const int tapoff = (t4 >> 1) * 81 + (t4 & 1) * 9;

    float d[6][4][4];
#pragma unroll
    for (int i = 0; i < 6; i++)
#pragma unroll
        for (int j = 0; j < 4; j++)
#pragma unroll
            for (int r = 0; r < 4; r++) d[i][j][r] = 0.f;

    // ---- conv GEMM: K = 512 (64 c x 8 taps), 8 chunks of 8 channels ----
    // A streams from L2 via LDG (table is hot: every CTA reads the same 768KB).
#pragma unroll 1
    for (int kc = 0; kc < 8; kc++) {
        if (kc == 4) {          // phase boundary: reload x tile with channels 32..63
            __syncthreads();    // all warps done reading phase 0
            load_half(1);
            __syncthreads();
        }
        const unsigned* Ak = gA + kc * 3072;
        const int cbase = (kc & 3) * 8;          // local channel base in this half

        unsigned bb[2][2][4];
        {
            const int cw = cbase * 405 + tapoff;
#pragma unroll
            for (int nt = 0; nt < 4; nt++) {
                bb[0][0][nt] = xt[cw + boff[nt]];
                bb[0][1][nt] = xt[cw + boff[nt] + 405];
            }
        }
#pragma unroll
        for (int cpi = 0; cpi < 4; cpi++) {
            const int cur = cpi & 1, nxt = cur ^ 1;
            if (cpi < 3) {
                const int cw = (cbase + 2 * (cpi + 1)) * 405 + tapoff;
#pragma unroll
                for (int nt = 0; nt < 4; nt++) {
                    bb[nxt][0][nt] = xt[cw + boff[nt]];
                    bb[nxt][1][nt] = xt[cw + boff[nt] + 405];
                }
            }
#pragma unroll
            for (int mt = 0; mt < 6; mt++) {
                uint4 av = __ldg((const uint4*)(Ak + (cpi * 6 + mt) * 128));
                unsigned a[4] = {av.x, av.y, av.z, av.w};
#pragma unroll
                for (int nt = 0; nt < 4; nt++)
                    mma_f16(d[mt][nt], a, bb[cur][0][nt], bb[cur][1][nt]);
            }
        }
    }

    // ---- relu + bias1, stage R_t[vox][96ch] fp16 (stride 100) over xt ----
    __syncthreads();   // all B gathers from xt are done
    {
        __half* Rt = (__half*)xt;
#pragma unroll
        for (int mt = 0; mt < 6; mt++)
#pragma unroll
            for (int nt = 0; nt < 4; nt++)
#pragma unroll
                for (int r = 0; r < 4; r++) {
                    int m = mt * 16 + g + 8 * (r >> 1);
                    int vox = w * 32 + nt * 8 + 2 * t4 + (r & 1);
                    float v = fmaxf(d[mt][nt][r] + b1s[m & 31], 0.f);
                    Rt[vox * 100 + m] = __float2half(v);
                }
    }
    __syncthreads();

    // ---- combine GEMM: D2[32][256] = A2[32][96] * R ----
    float e[2][4][4];
#pragma unroll
    for (int i = 0; i < 2; i++)
#pragma unroll
        for (int j = 0; j < 4; j++)
#pragma unroll
            for (int r = 0; r < 4; r++) e[i][j][r] = 0.f;

#pragma unroll
    for (int k2 = 0; k2 < 6; k2++) {
        unsigned bb0[4], bb1[4];
#pragma unroll
        for (int nt = 0; nt < 4; nt++) {
            int col = w * 32 + nt * 8 + g;
            int base = col * 50 + k2 * 8 + t4;   // u32 index into R_t
            bb0[nt] = xt[base];
            bb1[nt] = xt[base + 4];
        }
#pragma unroll
        for (int mt = 0; mt < 2; mt++) {
            unsigned a[4];
            *(uint4*)a = *(const uint4*)(sA2 + (k2 * 2 + mt) * 128 + lane * 4);
#pragma unroll
            for (int nt = 0; nt < 4; nt++)
                mma_f16(e[mt][nt], a, bb0[nt], bb1[nt]);
        }
    }

    // ---- bias2 + relu + store ----
#pragma unroll
    for (int mt = 0; mt < 2; mt++)
#pragma unroll
        for (int nt = 0; nt < 4; nt++)
#pragma unroll
            for (int r = 0; r < 4; r++) {
                int o = mt * 16 + g + 8 * (r >> 1);
                int vox = w * 32 + nt * 8 + 2 * t4 + (r & 1);
                int vx = vox & 7, vy = (vox >> 3) & 7, vz = vox >> 6;
                int gx = 2 * (Px0 + vx) + qx;
                int gy = 2 * (Py0 + vy) + qy;
                int gz = 2 * (Pz0 + vz) + qz;
                out[o * 262144 + gz * 4096 + gy * 64 + gx] =
                    fmaxf(e[mt][nt][r] + b2s[o], 0.f);
            }
}

// ---------------- launch -----------------------------------------------------
extern "C" void kernel_launch(void* const* d_in, const int* in_sizes, int n_in,
                              void* d_out, int out_size) {
    const float* x      = (const float*)d_in[0];
    const float* w_def  = (const float*)d_in[1];
    const float* b_def  = (const float*)d_in[2];
    const float* bn1_g  = (const float*)d_in[3];
    const float* bn1_b  = (const float*)d_in[4];
    const float* bn1_m  = (const float*)d_in[5];
    const float* bn1_v  = (const float*)d_in[6];
    const float* w_comb = (const float*)d_in[7];
    const float* b_comb = (const float*)d_in[8];
    const float* bn2_g  = (const float*)d_in[9];
    const float* bn2_b  = (const float*)d_in[10];
    const float* bn2_m  = (const float*)d_in[11];
    const float* bn2_v  = (const float*)d_in[12];

    setup_all<<<dim3(64, 8), 192>>>(w_def, bn1_g, bn1_v, b_def, bn1_b, bn1_m,
                                    w_comb, b_comb, bn2_g, bn2_b, bn2_m, bn2_v);

    cudaFuncSetAttribute(conv_main, cudaFuncAttributeMaxDynamicSharedMemorySize,
                         SMEM_BYTES);
    conv_main<<<dim3(4, 4, 64), 256, SMEM_BYTES>>>(x, (float*)d_out);
}

// round 10
// speedup vs baseline: 1.0089x; 1.0089x over previous
#include <cuda_runtime.h>
#include <cuda_fp16.h>
#include <math.h>

// ---------------- device scratch (static: allocations are forbidden) -------
// Conv A operand, fp16x2 fragment-major for mma.m16n8k16:
// [par(8)][kc(8)][cpi(4)][mt(6)][lane(32)][r(4)]  (each u32 = fp16x2)
__device__ unsigned g_A16[8 * 8 * 3072];
// Combine A operand: [k2(6)][mt(2)][lane(32)][r(4)] fp16x2
__device__ unsigned g_A2[1536];
__device__ float g_bias1[32];
__device__ float g_bias2[32];

// ---------------- helpers ----------------------------------------------------
__device__ __forceinline__ void mma_f16(float* d, const unsigned* a,
                                        unsigned b0, unsigned b1) {
    asm volatile(
        "mma.sync.aligned.m16n8k16.row.col.f32.f16.f16.f32 "
        "{%0,%1,%2,%3}, {%4,%5,%6,%7}, {%8,%9}, {%0,%1,%2,%3};"
        : "+f"(d[0]), "+f"(d[1]), "+f"(d[2]), "+f"(d[3])
        : "r"(a[0]), "r"(a[1]), "r"(a[2]), "r"(a[3]), "r"(b0), "r"(b1));
}

// per-axis trilinear->original-grid collapse weights (fp32: exact small
// rationals; error ~1e-7 invisible under fp16 quantization)
__device__ __forceinline__ float hvalf(int q, int k, int e, float a) {
    if (q == 0) {
        if (k == 0) return e ? a : (1.0f - a);
        return e ? 1.0f : 0.0f;
    } else {
        if (k == 2) return e ? (1.0f - a) : a;
        return e ? 0.0f : 1.0f;
    }
}

// ---------------- merged setup kernel ----------------------------------------
// grid (64 c, 8 par), block 192 = 6 mt x 32 lanes.
__global__ void setup_all(const float* __restrict__ W,
                          const float* __restrict__ g1, const float* __restrict__ v1,
                          const float* __restrict__ b_def,
                          const float* __restrict__ b1, const float* __restrict__ m1,
                          const float* __restrict__ wcm, const float* __restrict__ bcm,
                          const float* __restrict__ g2, const float* __restrict__ b2,
                          const float* __restrict__ m2, const float* __restrict__ v2) {
    __shared__ float ws[32 * 27];
    int c = blockIdx.x, par = blockIdx.y;
    int tid = threadIdx.x;
    for (int idx = tid; idx < 32 * 27; idx += 192) {
        int co = idx / 27, kk = idx - co * 27;
        ws[idx] = W[co * 1728 + c * 27 + kk];
    }
    __syncthreads();

    int mt = tid >> 5, lane = tid & 31;
    int g = lane >> 2, t4 = lane & 3;
    int qz = (par >> 2) & 1, qy = (par >> 1) & 1, qx = par & 1;

#pragma unroll
    for (int rowbit = 0; rowbit < 2; rowbit++) {
        int m = mt * 16 + g + 8 * rowbit;
        int br = m >> 5, co = m & 31;
        float a = (br == 0) ? 0.0f : (br == 1 ? 0.4f : 0.7f);
        float s1 = g1[co] * rsqrtf(v1[co] + 1e-5f);
        __half hh[2];
#pragma unroll
        for (int h = 0; h < 2; h++) {
            int tap = 2 * t4 + h;
            int ez = (tap >> 2) & 1, ey = (tap >> 1) & 1, ex = tap & 1;
            float hz[3], hy[3], hx[3];
#pragma unroll
            for (int k = 0; k < 3; k++) {
                hz[k] = hvalf(qz, k, ez, a);
                hy[k] = hvalf(qy, k, ey, a);
                hx[k] = hvalf(qx, k, ex, a);
            }
            float sum = 0.f;
#pragma unroll
            for (int kz = 0; kz < 3; kz++)
#pragma unroll
                for (int ky = 0; ky < 3; ky++)
#pragma unroll
                    for (int kx = 0; kx < 3; kx++)
                        sum += ws[co * 27 + kz * 9 + ky * 3 + kx] *
                               (hz[kz] * hy[ky] * hx[kx]);
            hh[h] = __float2half(sum * s1);
        }
        int r = 2 * (c & 1) + rowbit;
        int idx = ((((par * 8 + (c >> 3)) * 4 + ((c >> 1) & 3)) * 6 + mt) * 32 + lane) * 4 + r;
        __half2 hv = __halves2half2(hh[0], hh[1]);
        g_A16[idx] = *(unsigned*)&hv;
    }

    if (blockIdx.x == 0 && blockIdx.y == 0) {
        if (tid < 32) {
            float s1 = g1[tid] * rsqrtf(v1[tid] + 1e-5f);
            g_bias1[tid] = b_def[tid] * s1 + b1[tid] - m1[tid] * s1;
            float s2 = g2[tid] * rsqrtf(v2[tid] + 1e-5f);
            g_bias2[tid] = bcm[tid] * s2 + b2[tid] - m2[tid] * s2;
        }
        for (int idx = tid; idx < 1536; idx += 192) {
            int r = idx & 3, ln = (idx >> 2) & 31, mt2 = (idx >> 7) & 1, k2 = idx >> 8;
            int gg = ln >> 2, tt = ln & 3;
            int m = mt2 * 16 + gg + 8 * (r & 1);
            float s2 = g2[m] * rsqrtf(v2[m] + 1e-5f);
            int ch0 = k2 * 16 + 8 * (r >> 1) + 2 * tt;
            __half2 hv = __halves2half2(__float2half(wcm[m * 96 + ch0] * s2),
                                        __float2half(wcm[m * 96 + ch0 + 1] * s2));
            g_A2[idx] = *(unsigned*)&hv;
        }
    }
}

// ---------------- main fused kernel ------------------------------------------
// block 256 thr = 8 warps; tile = 8(x) x 8(y) x 4(z) orig coords = 256 voxels,
// one parity class. x tile held 32 channels at a time (2 phases) as overlapping
// fp16x2 pairs in smem. A fragments are LDG'd straight from the L2-hot table:
// NO smem staging, NO barriers in the kc loop — warps run fully independent.
#define XT_U32 12960            // 32c * 405 positions (fp16x2 pairs)
#define SA2_U32 1536
#define SMEM_BYTES ((XT_U32 + SA2_U32 + 64) * 4)

__global__ void __launch_bounds__(256, 2)
conv_main(const float* __restrict__ x, float* __restrict__ out) {
    extern __shared__ unsigned smu[];
    unsigned* xt = smu;                         // also R_t after conv
    unsigned* sA2 = smu + XT_U32;
    float* b1s = (float*)(sA2 + SA2_U32);
    float* b2s = b1s + 32;

    const int tid = threadIdx.x;
    const int w = tid >> 5, lane = tid & 31;
    const int g = lane >> 2, t4 = lane & 3;

    const int par = blockIdx.z >> 3;
    const int pzt = blockIdx.z & 7;
    const int qz = (par >> 2) & 1, qy = (par >> 1) & 1, qx = par & 1;
    const int Px0 = blockIdx.x * 8, Py0 = blockIdx.y * 8, Pz0 = pzt * 4;
    const int ox = Px0 - 1 + qx, oy = Py0 - 1 + qy, oz = Pz0 - 1 + qz;

    const unsigned* gA = g_A16 + par * 24576 + lane * 4;   // per-lane base

    // ---- hoisted loader coords: 2 fixed tile positions per thread ----
    const int p0 = tid;                       // 0..255 (<405 always)
    int z0 = p0 / 81, r0 = p0 - z0 * 81, y0 = r0 / 9, x0 = r0 - y0 * 9;
    int gz0 = oz + z0, gy0 = oy + y0, gx0 = ox + x0;
    const bool ok0 = ((unsigned)gz0 < 32u) && ((unsigned)gy0 < 32u) &&
                     ((unsigned)gx0 < 32u);
    const int off0 = (gz0 * 32 + gy0) * 32 + gx0;

    const int p1 = tid + 256;
    const bool has1 = p1 < 405;
    int z1 = p1 / 81, r1 = p1 - z1 * 81, y1 = r1 / 9, x1 = r1 - y1 * 9;
    int gz1 = oz + z1, gy1 = oy + y1, gx1 = ox + x1;
    const bool ok1 = has1 && ((unsigned)gz1 < 32u) && ((unsigned)gy1 < 32u) &&
                     ((unsigned)gx1 < 32u);
    const int off1 = (gz1 * 32 + gy1) * 32 + gx1;

    // x tile as overlapping fp16 pairs: pair idx holds halves (pos, pos+1)
    auto load_half = [&](int phase) {
        const float* xb = x + phase * 32 * 32768;
        __half* hp = (__half*)xt;
#pragma unroll 8
        for (int c = 0; c < 32; c++) {
            float v0 = ok0 ? __ldg(xb + c * 32768 + off0) : 0.f;
            __half h0 = __float2half(v0);
            int i0 = c * 405 + p0;
            hp[2 * i0] = h0;
            if (p0) hp[2 * i0 - 1] = h0;
            if (has1) {
                float v1v = ok1 ? __ldg(xb + c * 32768 + off1) : 0.f;
                __half h1 = __float2half(v1v);
                int i1 = c * 405 + p1;
                hp[2 * i1] = h1;
                hp[2 * i1 - 1] = h1;
            }
        }
    };

    load_half(0);
    for (int i = tid; i < SA2_U32; i += 256) sA2[i] = g_A2[i];
    if (tid < 32) { b1s[tid] = g_bias1[tid]; b2s[tid] = g_bias2[tid]; }
    __syncthreads();

    // ---- per-lane B gather offsets ----
    int boff[4];
#pragma unroll
    for (int nt = 0; nt < 4; nt++) {
        int vox = w * 32 + nt * 8 + g;
        boff[nt] = (vox >> 6) * 81 + ((vox >> 3) & 7) * 9 + (vox & 7);
    }
    const int tapoff = (t4 >> 1) * 81 + (t4 & 1) * 9;

    float d[6][4][4];
#pragma unroll
    for (int i = 0; i < 6; i++)
#pragma unroll
        for (int j = 0; j < 4; j++)
#pragma unroll
            for (int r = 0; r < 4; r++) d[i][j][r] = 0.f;

    // ---- conv GEMM: K = 512 (64 c x 8 taps), 8 chunks of 8 channels ----
    // A streams from L2 via LDG (table is hot: every CTA reads the same 768KB).
#pragma unroll 1
    for (int kc = 0; kc < 8; kc++) {
        if (kc == 4) {          // phase boundary: reload x tile with channels 32..63
            __syncthreads();    // all warps done reading phase 0
            load_half(1);
            __syncthreads();
        }
        const unsigned* Ak = gA + kc * 3072;
        const int cbase = (kc & 3) * 8;          // local channel base in this half

        unsigned bb[2][2][4];
        {
            const int cw = cbase * 405 + tapoff;
#pragma unroll
            for (int nt = 0; nt < 4; nt++) {
                bb[0][0][nt] = xt[cw + boff[nt]];
                bb[0][1][nt] = xt[cw + boff[nt] + 405];
            }
        }
#pragma unroll
        for (int cpi = 0; cpi < 4; cpi++) {
            const int cur = cpi & 1, nxt = cur ^ 1;
            if (cpi < 3) {
                const int cw = (cbase + 2 * (cpi + 1)) * 405 + tapoff;
#pragma unroll
                for (int nt = 0; nt < 4; nt++) {
                    bb[nxt][0][nt] = xt[cw + boff[nt]];
                    bb[nxt][1][nt] = xt[cw + boff[nt] + 405];
                }
            }
#pragma unroll
            for (int mt = 0; mt < 6; mt++) {
                uint4 av = __ldg((const uint4*)(Ak + (cpi * 6 + mt) * 128));
                unsigned a[4] = {av.x, av.y, av.z, av.w};
#pragma unroll
                for (int nt = 0; nt < 4; nt++)
                    mma_f16(d[mt][nt], a, bb[cur][0][nt], bb[cur][1][nt]);
            }
        }
    }

    // ---- relu + bias1, stage R_t[vox][96ch] fp16 (stride 100) over xt ----
    __syncthreads();   // all B gathers from xt are done
    {
        __half* Rt = (__half*)xt;
#pragma unroll
        for (int mt = 0; mt < 6; mt++)
#pragma unroll
            for (int nt = 0; nt < 4; nt++)
#pragma unroll
                for (int r = 0; r < 4; r++) {
                    int m = mt * 16 + g + 8 * (r >> 1);
                    int vox = w * 32 + nt * 8 + 2 * t4 + (r & 1);
                    float v = fmaxf(d[mt][nt][r] + b1s[m & 31], 0.f);
                    Rt[vox * 100 + m] = __float2half(v);
                }
    }
    __syncthreads();

    // ---- combine GEMM: D2[32][256] = A2[32][96] * R ----
    float e[2][4][4];
#pragma unroll
    for (int i = 0; i < 2; i++)
#pragma unroll
        for (int j = 0; j < 4; j++)
#pragma unroll
            for (int r = 0; r < 4; r++) e[i][j][r] = 0.f;

#pragma unroll
    for (int k2 = 0; k2 < 6; k2++) {
        unsigned bb0[4], bb1[4];
#pragma unroll
        for (int nt = 0; nt < 4; nt++) {
            int col = w * 32 + nt * 8 + g;
            int base = col * 50 + k2 * 8 + t4;   // u32 index into R_t
            bb0[nt] = xt[base];
            bb1[nt] = xt[base + 4];
        }
#pragma unroll
        for (int mt = 0; mt < 2; mt++) {
            unsigned a[4];
            *(uint4*)a = *(const uint4*)(sA2 + (k2 * 2 + mt) * 128 + lane * 4);
#pragma unroll
            for (int nt = 0; nt < 4; nt++)
                mma_f16(e[mt][nt], a, bb0[nt], bb1[nt]);
        }
    }

    // ---- bias2 + relu + store ----
#pragma unroll
    for (int mt = 0; mt < 2; mt++)
#pragma unroll
        for (int nt = 0; nt < 4; nt++)
#pragma unroll
            for (int r = 0; r < 4; r++) {
                int o = mt * 16 + g + 8 * (r >> 1);
                int vox = w * 32 + nt * 8 + 2 * t4 + (r & 1);
                int vx = vox & 7, vy = (vox >> 3) & 7, vz = vox >> 6;
                int gx = 2 * (Px0 + vx) + qx;
                int gy = 2 * (Py0 + vy) + qy;
                int gz = 2 * (Pz0 + vz) + qz;
                out[o * 262144 + gz * 4096 + gy * 64 + gx] =
                    fmaxf(e[mt][nt][r] + b2s[o], 0.f);
            }
}

// ---------------- launch -----------------------------------------------------
extern "C" void kernel_launch(void* const* d_in, const int* in_sizes, int n_in,
                              void* d_out, int out_size) {
    const float* x      = (const float*)d_in[0];
    const float* w_def  = (const float*)d_in[1];
    const float* b_def  = (const float*)d_in[2];
    const float* bn1_g  = (const float*)d_in[3];
    const float* bn1_b  = (const float*)d_in[4];
    const float* bn1_m  = (const float*)d_in[5];
    const float* bn1_v  = (const float*)d_in[6];
    const float* w_comb = (const float*)d_in[7];
    const float* b_comb = (const float*)d_in[8];
    const float* bn2_g  = (const float*)d_in[9];
    const float* bn2_b  = (const float*)d_in[10];
    const float* bn2_m  = (const float*)d_in[11];
    const float* bn2_v  = (const float*)d_in[12];

    setup_all<<<dim3(64, 8), 192>>>(w_def, bn1_g, bn1_v, b_def, bn1_b, bn1_m,
                                    w_comb, b_comb, bn2_g, bn2_b, bn2_m, bn2_v);

    cudaFuncSetAttribute(conv_main, cudaFuncAttributeMaxDynamicSharedMemorySize,
                         SMEM_BYTES);
    conv_main<<<dim3(4, 4, 64), 256, SMEM_BYTES>>>(x, (float*)d_out);
}

// round 12
// speedup vs baseline: 1.5569x; 1.5431x over previous
#include <cuda_runtime.h>
#include <cuda_fp16.h>
#include <math.h>

// ---------------- device scratch (static: allocations are forbidden) -------
// Conv A operand, fp16x2 fragment-major for mma.m16n8k16:
// [par(8)][kc(8)][cpi(4)][mt(6)][lane(32)][r(4)]  (each u32 = fp16x2)
__device__ unsigned g_A16[8 * 8 * 3072];
// Combine A operand: [k2(6)][mt(2)][lane(32)][r(4)] fp16x2
__device__ unsigned g_A2[1536];
__device__ float g_bias1[32];
__device__ float g_bias2[32];

// ---------------- helpers ----------------------------------------------------
__device__ __forceinline__ void mma_f16(float* d, const unsigned* a,
                                        unsigned b0, unsigned b1) {
    asm volatile(
        "mma.sync.aligned.m16n8k16.row.col.f32.f16.f16.f32 "
        "{%0,%1,%2,%3}, {%4,%5,%6,%7}, {%8,%9}, {%0,%1,%2,%3};"
        : "+f"(d[0]), "+f"(d[1]), "+f"(d[2]), "+f"(d[3])
        : "r"(a[0]), "r"(a[1]), "r"(a[2]), "r"(a[3]), "r"(b0), "r"(b1));
}
__device__ __forceinline__ void mbar_init(unsigned mbar, unsigned count) {
    asm volatile("mbarrier.init.shared.b64 [%0], %1;" :: "r"(mbar), "r"(count)
                 : "memory");
}
__device__ __forceinline__ void mbar_expect_tx(unsigned mbar, unsigned bytes) {
    asm volatile("mbarrier.arrive.expect_tx.shared.b64 _, [%0], %1;"
                 :: "r"(mbar), "r"(bytes) : "memory");
}
__device__ __forceinline__ void mbar_wait(unsigned mbar, unsigned parity) {
    asm volatile(
        "{\n\t.reg .pred P1;\n\t"
        "WL_%=:\n\t"
        "mbarrier.try_wait.parity.acquire.cta.shared::cta.b64 P1, [%0], %1, 0x989680;\n\t"
        "@P1 bra.uni WD_%=;\n\t"
        "bra.uni WL_%=;\n\t"
        "WD_%=:\n\t}"
        :: "r"(mbar), "r"(parity) : "memory");
}
__device__ __forceinline__ void cp_bulk(unsigned dstS, const void* src,
                                        unsigned bytes, unsigned mbarS) {
    asm volatile(
        "cp.async.bulk.shared::cta.global.mbarrier::complete_tx::bytes "
        "[%0], [%1], %2, [%3];"
        :: "r"(dstS), "l"(src), "r"(bytes), "r"(mbarS) : "memory");
}
__device__ __forceinline__ unsigned smem_u32(const void* p) {
    return (unsigned)(unsigned long long)__cvta_generic_to_shared(p);
}

// per-axis trilinear->original-grid collapse weights (fp32: exact small
// rationals; error ~1e-7 invisible under fp16 quantization)
__device__ __forceinline__ float hvalf(int q, int k, int e, float a) {
    if (q == 0) {
        if (k == 0) return e ? a : (1.0f - a);
        return e ? 1.0f : 0.0f;
    } else {
        if (k == 2) return e ? (1.0f - a) : a;
        return e ? 0.0f : 1.0f;
    }
}

// ---------------- merged setup kernel ----------------------------------------
// grid (64 c, 8 par), block 192 = 6 mt x 32 lanes.
__global__ void setup_all(const float* __restrict__ W,
                          const float* __restrict__ g1, const float* __restrict__ v1,
                          const float* __restrict__ b_def,
                          const float* __restrict__ b1, const float* __restrict__ m1,
                          const float* __restrict__ wcm, const float* __restrict__ bcm,
                          const float* __restrict__ g2, const float* __restrict__ b2,
                          const float* __restrict__ m2, const float* __restrict__ v2) {
    __shared__ float ws[32 * 27];
    int c = blockIdx.x, par = blockIdx.y;
    int tid = threadIdx.x;
    for (int idx = tid; idx < 32 * 27; idx += 192) {
        int co = idx / 27, kk = idx - co * 27;
        ws[idx] = W[co * 1728 + c * 27 + kk];
    }
    __syncthreads();

    int mt = tid >> 5, lane = tid & 31;
    int g = lane >> 2, t4 = lane & 3;
    int qz = (par >> 2) & 1, qy = (par >> 1) & 1, qx = par & 1;

#pragma unroll
    for (int rowbit = 0; rowbit < 2; rowbit++) {
        int m = mt * 16 + g + 8 * rowbit;
        int br = m >> 5, co = m & 31;
        float a = (br == 0) ? 0.0f : (br == 1 ? 0.4f : 0.7f);
        float s1 = g1[co] * rsqrtf(v1[co] + 1e-5f);
        __half hh[2];
#pragma unroll
        for (int h = 0; h < 2; h++) {
            int tap = 2 * t4 + h;
            int ez = (tap >> 2) & 1, ey = (tap >> 1) & 1, ex = tap & 1;
            float hz[3], hy[3], hx[3];
#pragma unroll
            for (int k = 0; k < 3; k++) {
                hz[k] = hvalf(qz, k, ez, a);
                hy[k] = hvalf(qy, k, ey, a);
                hx[k] = hvalf(qx, k, ex, a);
            }
            float sum = 0.f;
#pragma unroll
            for (int kz = 0; kz < 3; kz++)
#pragma unroll
                for (int ky = 0; ky < 3; ky++)
#pragma unroll
                    for (int kx = 0; kx < 3; kx++)
                        sum += ws[co * 27 + kz * 9 + ky * 3 + kx] *
                               (hz[kz] * hy[ky] * hx[kx]);
            hh[h] = __float2half(sum * s1);
        }
        int r = 2 * (c & 1) + rowbit;
        int idx = ((((par * 8 + (c >> 3)) * 4 + ((c >> 1) & 3)) * 6 + mt) * 32 + lane) * 4 + r;
        __half2 hv = __halves2half2(hh[0], hh[1]);
        g_A16[idx] = *(unsigned*)&hv;
    }

    if (blockIdx.x == 0 && blockIdx.y == 0) {
        if (tid < 32) {
            float s1 = g1[tid] * rsqrtf(v1[tid] + 1e-5f);
            g_bias1[tid] = b_def[tid] * s1 + b1[tid] - m1[tid] * s1;
            float s2 = g2[tid] * rsqrtf(v2[tid] + 1e-5f);
            g_bias2[tid] = bcm[tid] * s2 + b2[tid] - m2[tid] * s2;
        }
        for (int idx = tid; idx < 1536; idx += 192) {
            int r = idx & 3, ln = (idx >> 2) & 31, mt2 = (idx >> 7) & 1, k2 = idx >> 8;
            int gg = ln >> 2, tt = ln & 3;
            int m = mt2 * 16 + gg + 8 * (r & 1);
            float s2 = g2[m] * rsqrtf(v2[m] + 1e-5f);
            int ch0 = k2 * 16 + 8 * (r >> 1) + 2 * tt;
            __half2 hv = __halves2half2(__float2half(wcm[m * 96 + ch0] * s2),
                                        __float2half(wcm[m * 96 + ch0 + 1] * s2));
            g_A2[idx] = *(unsigned*)&hv;
        }
    }
}

// ---------------- main fused kernel ------------------------------------------
// block 256 thr = 8 warps; tile = 8(x) x 8(y) x 2(z) orig coords = 128 voxels,
// one parity class. Small tile -> 48 conv accumulators/thread -> 3 CTAs/SM.
// x tile: 32-channel phases (2), zdim 3 -> 243 positions, overlapping fp16x2.
// A chunks: cp.async.bulk double buffer, R7 scheme (prefetch 0; refill kc+1
// at iteration kc, AFTER the top-of-loop __syncthreads drains buffer (kc+1)&1).
#define XT_U32 7776             // 32c * 243 positions
#define SA2_OFF 7776
#define B1S_OFF 9312
#define B2S_OFF 9344
#define SA_OFF 9376             // 2 x 3072 u32 A double buffer (16B aligned)
#define MBAR_OFF 15520          // 2 mbarriers (byte 62080, 8-aligned)
#define SMEM_U32 15524
#define SMEM_BYTES (SMEM_U32 * 4)
#define A_CHUNK_BYTES 12288

__global__ void __launch_bounds__(256, 3)
conv_main(const float* __restrict__ x, float* __restrict__ out) {
    extern __shared__ unsigned smu[];
    unsigned* xt = smu;                         // also R_t after conv
    unsigned* sA2 = smu + SA2_OFF;
    float* b1s = (float*)(smu + B1S_OFF);
    float* b2s = (float*)(smu + B2S_OFF);
    unsigned* sA = smu + SA_OFF;

    const unsigned base_u32 = smem_u32(smu);
    const unsigned mbar = base_u32 + MBAR_OFF * 4;
    const unsigned sA_addr = base_u32 + SA_OFF * 4;

    const int tid = threadIdx.x;
    const int w = tid >> 5, lane = tid & 31;
    const int g = lane >> 2, t4 = lane & 3;

    const int par = blockIdx.z >> 4;
    const int pzt = blockIdx.z & 15;
    const int qz = (par >> 2) & 1, qy = (par >> 1) & 1, qx = par & 1;
    const int Px0 = blockIdx.x * 8, Py0 = blockIdx.y * 8, Pz0 = pzt * 2;
    const int ox = Px0 - 1 + qx, oy = Py0 - 1 + qy, oz = Pz0 - 1 + qz;

    const unsigned* gA = g_A16 + par * 24576;

    // ---- mbarriers + prefetch A chunk 0 ONLY (R7 scheme) ----
    if (tid == 0) {
        mbar_init(mbar + 0, 1);
        mbar_init(mbar + 8, 1);
    }
    __syncthreads();
    if (tid == 0) {
        mbar_expect_tx(mbar, A_CHUNK_BYTES);
        cp_bulk(sA_addr, gA, A_CHUNK_BYTES, mbar);
    }

    // ---- hoisted loader coords: 1 tile position per thread (243 used) ----
    const int p0 = tid;
    const bool has0 = p0 < 243;
    int z0 = p0 / 81, r0 = p0 - z0 * 81, y0 = r0 / 9, x0 = r0 - y0 * 9;
    int gz0 = oz + z0, gy0 = oy + y0, gx0 = ox + x0;
    const bool ok0 = has0 && ((unsigned)gz0 < 32u) && ((unsigned)gy0 < 32u) &&
                     ((unsigned)gx0 < 32u);
    const int off0 = (gz0 * 32 + gy0) * 32 + gx0;

    // x tile as overlapping fp16 pairs: pair idx holds halves (pos, pos+1)
    auto load_half = [&](int phase) {
        const float* xb = x + phase * 32 * 32768;
        __half* hp = (__half*)xt;
        if (has0) {
#pragma unroll 8
            for (int c = 0; c < 32; c++) {
                float v0 = ok0 ? __ldg(xb + c * 32768 + off0) : 0.f;
                __half h0 = __float2half(v0);
                int i0 = c * 243 + p0;
                hp[2 * i0] = h0;
                if (p0) hp[2 * i0 - 1] = h0;
            }
        }
    };

    load_half(0);
    for (int i = tid; i < 1536; i += 256) sA2[i] = g_A2[i];
    if (tid < 32) { b1s[tid] = g_bias1[tid]; b2s[tid] = g_bias2[tid]; }
    __syncthreads();

    // ---- per-lane B gather offsets (warp covers 16 voxels: nt=0,1) ----
    int boff[2];
#pragma unroll
    for (int nt = 0; nt < 2; nt++) {
        int vox = w * 16 + nt * 8 + g;
        boff[nt] = (vox >> 6) * 81 + ((vox >> 3) & 7) * 9 + (vox & 7);
    }
    const int tapoff = (t4 >> 1) * 81 + (t4 & 1) * 9;

    float d[6][2][4];
#pragma unroll
    for (int i = 0; i < 6; i++)
#pragma unroll
        for (int j = 0; j < 2; j++)
#pragma unroll
            for (int r = 0; r < 4; r++) d[i][j][r] = 0.f;

    // ---- conv GEMM: K = 512 (64 c x 8 taps), 8 chunks of 8 channels ----
#pragma unroll 1
    for (int kc = 0; kc < 8; kc++) {
        mbar_wait(mbar + (kc & 1) * 8, (kc >> 1) & 1);
        __syncthreads();   // all warps done with buffer (kc+1)&1 (iter kc-1)
        if (tid == 0 && kc < 7) {
            unsigned mb = mbar + ((kc + 1) & 1) * 8;
            mbar_expect_tx(mb, A_CHUNK_BYTES);
            cp_bulk(sA_addr + ((kc + 1) & 1) * A_CHUNK_BYTES,
                    gA + (kc + 1) * 3072, A_CHUNK_BYTES, mb);
        }
        if (kc == 4) {          // phase boundary: channels 32..63
            load_half(1);
            __syncthreads();
        }
        const unsigned* Ab = sA + (kc & 1) * 3072;
        const int cbase = (kc & 3) * 8;

        unsigned bb[2][2][2];
        {
            const int cw = cbase * 243 + tapoff;
#pragma unroll
            for (int nt = 0; nt < 2; nt++) {
                bb[0][0][nt] = xt[cw + boff[nt]];
                bb[0][1][nt] = xt[cw + boff[nt] + 243];
            }
        }
#pragma unroll
        for (int cpi = 0; cpi < 4; cpi++) {
            const int cur = cpi & 1, nxt = cur ^ 1;
            if (cpi < 3) {
                const int cw = (cbase + 2 * (cpi + 1)) * 243 + tapoff;
#pragma unroll
                for (int nt = 0; nt < 2; nt++) {
                    bb[nxt][0][nt] = xt[cw + boff[nt]];
                    bb[nxt][1][nt] = xt[cw + boff[nt] + 243];
                }
            }
#pragma unroll
            for (int mt = 0; mt < 6; mt++) {
                unsigned a[4];
                *(uint4*)a = *(const uint4*)(Ab + (cpi * 6 + mt) * 128 + lane * 4);
#pragma unroll
                for (int nt = 0; nt < 2; nt++)
                    mma_f16(d[mt][nt], a, bb[cur][0][nt], bb[cur][1][nt]);
            }
        }
    }

    // ---- relu + bias1, stage R_t[vox][96ch] fp16 (stride 100) over xt ----
    __syncthreads();
    {
        __half* Rt = (__half*)xt;
#pragma unroll
        for (int mt = 0; mt < 6; mt++)
#pragma unroll
            for (int nt = 0; nt < 2; nt++)
#pragma unroll
                for (int r = 0; r < 4; r++) {
                    int m = mt * 16 + g + 8 * (r >> 1);
                    int vox = w * 16 + nt * 8 + 2 * t4 + (r & 1);
                    float v = fmaxf(d[mt][nt][r] + b1s[m & 31], 0.f);
                    Rt[vox * 100 + m] = __float2half(v);
                }
    }
    __syncthreads();

    // ---- combine GEMM: D2[32][128] = A2[32][96] * R ----
    float e[2][2][4];
#pragma unroll
    for (int i = 0; i < 2; i++)
#pragma unroll
        for (int j = 0; j < 2; j++)
#pragma unroll
            for (int r = 0; r < 4; r++) e[i][j][r] = 0.f;

#pragma unroll
    for (int k2 = 0; k2 < 6; k2++) {
        unsigned bb0[2], bb1[2];
#pragma unroll
        for (int nt = 0; nt < 2; nt++) {
            int col = w * 16 + nt * 8 + g;
            int base = col * 50 + k2 * 8 + t4;
            bb0[nt] = xt[base];
            bb1[nt] = xt[base + 4];
        }
#pragma unroll
        for (int mt = 0; mt < 2; mt++) {
            unsigned a[4];
            *(uint4*)a = *(const uint4*)(sA2 + (k2 * 2 + mt) * 128 + lane * 4);
#pragma unroll
            for (int nt = 0; nt < 2; nt++)
                mma_f16(e[mt][nt], a, bb0[nt], bb1[nt]);
        }
    }

    // ---- bias2 + relu + store ----
#pragma unroll
    for (int mt = 0; mt < 2; mt++)
#pragma unroll
        for (int nt = 0; nt < 2; nt++)
#pragma unroll
            for (int r = 0; r < 4; r++) {
                int o = mt * 16 + g + 8 * (r >> 1);
                int vox = w * 16 + nt * 8 + 2 * t4 + (r & 1);
                int vx = vox & 7, vy = (vox >> 3) & 7, vz = vox >> 6;
                int gx = 2 * (Px0 + vx) + qx;
                int gy = 2 * (Py0 + vy) + qy;
                int gz = 2 * (Pz0 + vz) + qz;
                out[o * 262144 + gz * 4096 + gy * 64 + gx] =
                    fmaxf(e[mt][nt][r] + b2s[o], 0.f);
            }
}

// ---------------- launch -----------------------------------------------------
extern "C" void kernel_launch(void* const* d_in, const int* in_sizes, int n_in,
                              void* d_out, int out_size) {
    const float* x      = (const float*)d_in[0];
    const float* w_def  = (const float*)d_in[1];
    const float* b_def  = (const float*)d_in[2];
    const float* bn1_g  = (const float*)d_in[3];
    const float* bn1_b  = (const float*)d_in[4];
    const float* bn1_m  = (const float*)d_in[5];
    const float* bn1_v  = (const float*)d_in[6];
    const float* w_comb = (const float*)d_in[7];
    const float* b_comb = (const float*)d_in[8];
    const float* bn2_g  = (const float*)d_in[9];
    const float* bn2_b  = (const float*)d_in[10];
    const float* bn2_m  = (const float*)d_in[11];
    const float* bn2_v  = (const float*)d_in[12];

    setup_all<<<dim3(64, 8), 192>>>(w_def, bn1_g, bn1_v, b_def, bn1_b, bn1_m,
                                    w_comb, b_comb, bn2_g, bn2_b, bn2_m, bn2_v);

    cudaFuncSetAttribute(conv_main, cudaFuncAttributeMaxDynamicSharedMemorySize,
                         SMEM_BYTES);
    conv_main<<<dim3(4, 4, 128), 256, SMEM_BYTES>>>(x, (float*)d_out);
}

// round 13
// speedup vs baseline: 1.6090x; 1.0335x over previous
#include <cuda_runtime.h>
#include <cuda_fp16.h>
#include <math.h>

// ---------------- device scratch (static: allocations are forbidden) -------
// Conv A operand, fp16x2 fragment-major for mma.m16n8k16:
// [par(8)][kc(8)][cpi(4)][mt(6)][lane(32)][r(4)]  (each u32 = fp16x2)
__device__ unsigned g_A16[8 * 8 * 3072];
// Combine A operand: [k2(6)][mt(2)][lane(32)][r(4)] fp16x2
__device__ unsigned g_A2[1536];
__device__ float g_bias1[32];
__device__ float g_bias2[32];

// ---------------- helpers ----------------------------------------------------
__device__ __forceinline__ void mma_f16(float* d, const unsigned* a,
                                        unsigned b0, unsigned b1) {
    asm volatile(
        "mma.sync.aligned.m16n8k16.row.col.f32.f16.f16.f32 "
        "{%0,%1,%2,%3}, {%4,%5,%6,%7}, {%8,%9}, {%0,%1,%2,%3};"
        : "+f"(d[0]), "+f"(d[1]), "+f"(d[2]), "+f"(d[3])
        : "r"(a[0]), "r"(a[1]), "r"(a[2]), "r"(a[3]), "r"(b0), "r"(b1));
}
__device__ __forceinline__ void mbar_init(unsigned mbar, unsigned count) {
    asm volatile("mbarrier.init.shared.b64 [%0], %1;" :: "r"(mbar), "r"(count)
                 : "memory");
}
__device__ __forceinline__ void mbar_expect_tx(unsigned mbar, unsigned bytes) {
    asm volatile("mbarrier.arrive.expect_tx.shared.b64 _, [%0], %1;"
                 :: "r"(mbar), "r"(bytes) : "memory");
}
__device__ __forceinline__ void mbar_wait(unsigned mbar, unsigned parity) {
    asm volatile(
        "{\n\t.reg .pred P1;\n\t"
        "WL_%=:\n\t"
        "mbarrier.try_wait.parity.acquire.cta.shared::cta.b64 P1, [%0], %1, 0x989680;\n\t"
        "@P1 bra.uni WD_%=;\n\t"
        "bra.uni WL_%=;\n\t"
        "WD_%=:\n\t}"
        :: "r"(mbar), "r"(parity) : "memory");
}
__device__ __forceinline__ void cp_bulk(unsigned dstS, const void* src,
                                        unsigned bytes, unsigned mbarS) {
    asm volatile(
        "cp.async.bulk.shared::cta.global.mbarrier::complete_tx::bytes "
        "[%0], [%1], %2, [%3];"
        :: "r"(dstS), "l"(src), "r"(bytes), "r"(mbarS) : "memory");
}
__device__ __forceinline__ unsigned smem_u32(const void* p) {
    return (unsigned)(unsigned long long)__cvta_generic_to_shared(p);
}

// per-axis trilinear->original-grid collapse weights (fp32: exact small
// rationals; error ~1e-7 invisible under fp16 quantization)
__device__ __forceinline__ float hvalf(int q, int k, int e, float a) {
    if (q == 0) {
        if (k == 0) return e ? a : (1.0f - a);
        return e ? 1.0f : 0.0f;
    } else {
        if (k == 2) return e ? (1.0f - a) : a;
        return e ? 0.0f : 1.0f;
    }
}

// ---------------- merged setup kernel ----------------------------------------
// grid (64 c, 8 par), block 192 = 6 mt x 32 lanes.
__global__ void setup_all(const float* __restrict__ W,
                          const float* __restrict__ g1, const float* __restrict__ v1,
                          const float* __restrict__ b_def,
                          const float* __restrict__ b1, const float* __restrict__ m1,
                          const float* __restrict__ wcm, const float* __restrict__ bcm,
                          const float* __restrict__ g2, const float* __restrict__ b2,
                          const float* __restrict__ m2, const float* __restrict__ v2) {
    __shared__ float ws[32 * 27];
    int c = blockIdx.x, par = blockIdx.y;
    int tid = threadIdx.x;
    for (int idx = tid; idx < 32 * 27; idx += 192) {
        int co = idx / 27, kk = idx - co * 27;
        ws[idx] = W[co * 1728 + c * 27 + kk];
    }
    __syncthreads();

    int mt = tid >> 5, lane = tid & 31;
    int g = lane >> 2, t4 = lane & 3;
    int qz = (par >> 2) & 1, qy = (par >> 1) & 1, qx = par & 1;

#pragma unroll
    for (int rowbit = 0; rowbit < 2; rowbit++) {
        int m = mt * 16 + g + 8 * rowbit;
        int br = m >> 5, co = m & 31;
        float a = (br == 0) ? 0.0f : (br == 1 ? 0.4f : 0.7f);
        float s1 = g1[co] * rsqrtf(v1[co] + 1e-5f);
        __half hh[2];
#pragma unroll
        for (int h = 0; h < 2; h++) {
            int tap = 2 * t4 + h;
            int ez = (tap >> 2) & 1, ey = (tap >> 1) & 1, ex = tap & 1;
            float hz[3], hy[3], hx[3];
#pragma unroll
            for (int k = 0; k < 3; k++) {
                hz[k] = hvalf(qz, k, ez, a);
                hy[k] = hvalf(qy, k, ey, a);
                hx[k] = hvalf(qx, k, ex, a);
            }
            float sum = 0.f;
#pragma unroll
            for (int kz = 0; kz < 3; kz++)
#pragma unroll
                for (int ky = 0; ky < 3; ky++)
#pragma unroll
                    for (int kx = 0; kx < 3; kx++)
                        sum += ws[co * 27 + kz * 9 + ky * 3 + kx] *
                               (hz[kz] * hy[ky] * hx[kx]);
            hh[h] = __float2half(sum * s1);
        }
        int r = 2 * (c & 1) + rowbit;
        int idx = ((((par * 8 + (c >> 3)) * 4 + ((c >> 1) & 3)) * 6 + mt) * 32 + lane) * 4 + r;
        __half2 hv = __halves2half2(hh[0], hh[1]);
        g_A16[idx] = *(unsigned*)&hv;
    }

    if (blockIdx.x == 0 && blockIdx.y == 0) {
        if (tid < 32) {
            float s1 = g1[tid] * rsqrtf(v1[tid] + 1e-5f);
            g_bias1[tid] = b_def[tid] * s1 + b1[tid] - m1[tid] * s1;
            float s2 = g2[tid] * rsqrtf(v2[tid] + 1e-5f);
            g_bias2[tid] = bcm[tid] * s2 + b2[tid] - m2[tid] * s2;
        }
        for (int idx = tid; idx < 1536; idx += 192) {
            int r = idx & 3, ln = (idx >> 2) & 31, mt2 = (idx >> 7) & 1, k2 = idx >> 8;
            int gg = ln >> 2, tt = ln & 3;
            int m = mt2 * 16 + gg + 8 * (r & 1);
            float s2 = g2[m] * rsqrtf(v2[m] + 1e-5f);
            int ch0 = k2 * 16 + 8 * (r >> 1) + 2 * tt;
            __half2 hv = __halves2half2(__float2half(wcm[m * 96 + ch0] * s2),
                                        __float2half(wcm[m * 96 + ch0 + 1] * s2));
            g_A2[idx] = *(unsigned*)&hv;
        }
    }
}

// ---------------- main fused kernel ------------------------------------------
// block 256 thr = 8 warps; tile = 8(x) x 8(y) x 2(z) orig coords = 128 voxels,
// one parity class; 3 CTAs/SM.
// x tile layout: [pos(243)][channel(32, +2 pad)] u32 fp16x2 position-pairs ->
// B fragments (ch c, c+1 at same pos) load as ONE LDS.64.
// A chunks: cp.async.bulk double buffer (R12 scheme), leader-wait + syncthreads.
#define XT_STRIDE 34
#define XT_U32 (243 * XT_STRIDE)    // 8262
#define SA2_OFF 8264
#define B1S_OFF 9800
#define B2S_OFF 9832
#define SA_OFF 9864                 // 2 x 3072 u32 A double buffer (16B aligned)
#define MBAR_OFF 16008              // 2 mbarriers (byte 64032, 8-aligned)
#define SMEM_U32 16012
#define SMEM_BYTES (SMEM_U32 * 4)
#define A_CHUNK_BYTES 12288

__global__ void __launch_bounds__(256, 3)
conv_main(const float* __restrict__ x, float* __restrict__ out) {
    extern __shared__ unsigned smu[];
    unsigned* xt = smu;                         // also R_t after conv
    unsigned* sA2 = smu + SA2_OFF;
    float* b1s = (float*)(smu + B1S_OFF);
    float* b2s = (float*)(smu + B2S_OFF);
    unsigned* sA = smu + SA_OFF;

    const unsigned base_u32 = smem_u32(smu);
    const unsigned mbar = base_u32 + MBAR_OFF * 4;
    const unsigned sA_addr = base_u32 + SA_OFF * 4;

    const int tid = threadIdx.x;
    const int w = tid >> 5, lane = tid & 31;
    const int g = lane >> 2, t4 = lane & 3;

    const int par = blockIdx.z >> 4;
    const int pzt = blockIdx.z & 15;
    const int qz = (par >> 2) & 1, qy = (par >> 1) & 1, qx = par & 1;
    const int Px0 = blockIdx.x * 8, Py0 = blockIdx.y * 8, Pz0 = pzt * 2;
    const int ox = Px0 - 1 + qx, oy = Py0 - 1 + qy, oz = Pz0 - 1 + qz;

    const unsigned* gA = g_A16 + par * 24576;

    // ---- mbarriers + prefetch A chunk 0 ONLY ----
    if (tid == 0) {
        mbar_init(mbar + 0, 1);
        mbar_init(mbar + 8, 1);
    }
    __syncthreads();
    if (tid == 0) {
        mbar_expect_tx(mbar, A_CHUNK_BYTES);
        cp_bulk(sA_addr, gA, A_CHUNK_BYTES, mbar);
    }

    // ---- hoisted loader coords: 1 tile position per thread (243 used) ----
    const int p0 = tid;
    const bool has0 = p0 < 243;
    int z0 = p0 / 81, r0 = p0 - z0 * 81, y0 = r0 / 9, x0 = r0 - y0 * 9;
    int gz0 = oz + z0, gy0 = oy + y0, gx0 = ox + x0;
    const bool ok0 = has0 && ((unsigned)gz0 < 32u) && ((unsigned)gy0 < 32u) &&
                     ((unsigned)gx0 < 32u);
    const int off0 = (gz0 * 32 + gy0) * 32 + gx0;

    // x tile: u32 at [pos][c] = fp16 pair (value at pos, value at pos+1) of ch c.
    // thread owning pos writes its value as low half of [pos][c] and as high
    // half of [pos-1][c].
    auto load_half = [&](int phase) {
        const float* xb = x + phase * 32 * 32768;
        __half* hp = (__half*)xt;
        if (has0) {
#pragma unroll 8
            for (int c = 0; c < 32; c++) {
                float v0 = ok0 ? __ldg(xb + c * 32768 + off0) : 0.f;
                __half h0 = __float2half(v0);
                int i0 = p0 * XT_STRIDE + c;
                hp[2 * i0] = h0;
                if (p0) hp[2 * (i0 - XT_STRIDE) + 1] = h0;
            }
        }
    };

    load_half(0);
    for (int i = tid; i < 1536; i += 256) sA2[i] = g_A2[i];
    if (tid < 32) { b1s[tid] = g_bias1[tid]; b2s[tid] = g_bias2[tid]; }
    __syncthreads();

    // ---- per-lane B gather positions (warp covers 16 voxels: nt=0,1) ----
    int bpos[2];
#pragma unroll
    for (int nt = 0; nt < 2; nt++) {
        int vox = w * 16 + nt * 8 + g;
        bpos[nt] = ((vox >> 6) * 81 + ((vox >> 3) & 7) * 9 + (vox & 7) +
                    (t4 >> 1) * 81 + (t4 & 1) * 9) * XT_STRIDE;
    }

    float d[6][2][4];
#pragma unroll
    for (int i = 0; i < 6; i++)
#pragma unroll
        for (int j = 0; j < 2; j++)
#pragma unroll
            for (int r = 0; r < 4; r++) d[i][j][r] = 0.f;

    // ---- conv GEMM: K = 512 (64 c x 8 taps), 8 chunks of 8 channels ----
#pragma unroll 1
    for (int kc = 0; kc < 8; kc++) {
        if (tid == 0) mbar_wait(mbar + (kc & 1) * 8, (kc >> 1) & 1);
        __syncthreads();   // A[kc] visible; all warps done with buffer (kc+1)&1
        if (tid == 0 && kc < 7) {
            unsigned mb = mbar + ((kc + 1) & 1) * 8;
            mbar_expect_tx(mb, A_CHUNK_BYTES);
            cp_bulk(sA_addr + ((kc + 1) & 1) * A_CHUNK_BYTES,
                    gA + (kc + 1) * 3072, A_CHUNK_BYTES, mb);
        }
        if (kc == 4) {          // phase boundary: channels 32..63
            load_half(1);
            __syncthreads();
        }
        const unsigned* Ab = sA + (kc & 1) * 3072;
        const int cbase = (kc & 3) * 8;

        uint2 bb[2][2];
        {
#pragma unroll
            for (int nt = 0; nt < 2; nt++)
                bb[0][nt] = *(const uint2*)(xt + bpos[nt] + cbase);
        }
#pragma unroll
        for (int cpi = 0; cpi < 4; cpi++) {
            const int cur = cpi & 1, nxt = cur ^ 1;
            if (cpi < 3) {
                const int cc = cbase + 2 * (cpi + 1);
#pragma unroll
                for (int nt = 0; nt < 2; nt++)
                    bb[nxt][nt] = *(const uint2*)(xt + bpos[nt] + cc);
            }
#pragma unroll
            for (int mt = 0; mt < 6; mt++) {
                unsigned a[4];
                *(uint4*)a = *(const uint4*)(Ab + (cpi * 6 + mt) * 128 + lane * 4);
#pragma unroll
                for (int nt = 0; nt < 2; nt++)
                    mma_f16(d[mt][nt], a, bb[cur][nt].x, bb[cur][nt].y);
            }
        }
    }

    // ---- relu + bias1, stage R_t[vox][96ch] fp16 (stride 100) over xt ----
    __syncthreads();
    {
        __half* Rt = (__half*)xt;
#pragma unroll
        for (int mt = 0; mt < 6; mt++)
#pragma unroll
            for (int nt = 0; nt < 2; nt++)
#pragma unroll
                for (int r = 0; r < 4; r++) {
                    int m = mt * 16 + g + 8 * (r >> 1);
                    int vox = w * 16 + nt * 8 + 2 * t4 + (r & 1);
                    float v = fmaxf(d[mt][nt][r] + b1s[m & 31], 0.f);
                    Rt[vox * 100 + m] = __float2half(v);
                }
    }
    __syncthreads();

    // ---- combine GEMM: D2[32][128] = A2[32][96] * R ----
    float e[2][2][4];
#pragma unroll
    for (int i = 0; i < 2; i++)
#pragma unroll
        for (int j = 0; j < 2; j++)
#pragma unroll
            for (int r = 0; r < 4; r++) e[i][j][r] = 0.f;

#pragma unroll
    for (int k2 = 0; k2 < 6; k2++) {
        unsigned bb0[2], bb1[2];
#pragma unroll
        for (int nt = 0; nt < 2; nt++) {
            int col = w * 16 + nt * 8 + g;
            int base = col * 50 + k2 * 8 + t4;
            bb0[nt] = xt[base];
            bb1[nt] = xt[base + 4];
        }
#pragma unroll
        for (int mt = 0; mt < 2; mt++) {
            unsigned a[4];
            *(uint4*)a = *(const uint4*)(sA2 + (k2 * 2 + mt) * 128 + lane * 4);
#pragma unroll
            for (int nt = 0; nt < 2; nt++)
                mma_f16(e[mt][nt], a, bb0[nt], bb1[nt]);
        }
    }

    // ---- bias2 + relu + store ----
#pragma unroll
    for (int mt = 0; mt < 2; mt++)
#pragma unroll
        for (int nt = 0; nt < 2; nt++)
#pragma unroll
            for (int r = 0; r < 4; r++) {
                int o = mt * 16 + g + 8 * (r >> 1);
                int vox = w * 16 + nt * 8 + 2 * t4 + (r & 1);
                int vx = vox & 7, vy = (vox >> 3) & 7, vz = vox >> 6;
                int gx = 2 * (Px0 + vx) + qx;
                int gy = 2 * (Py0 + vy) + qy;
                int gz = 2 * (Pz0 + vz) + qz;
                out[o * 262144 + gz * 4096 + gy * 64 + gx] =
                    fmaxf(e[mt][nt][r] + b2s[o], 0.f);
            }
}

// ---------------- launch -----------------------------------------------------
extern "C" void kernel_launch(void* const* d_in, const int* in_sizes, int n_in,
                              void* d_out, int out_size) {
    const float* x      = (const float*)d_in[0];
    const float* w_def  = (const float*)d_in[1];
    const float* b_def  = (const float*)d_in[2];
    const float* bn1_g  = (const float*)d_in[3];
    const float* bn1_b  = (const float*)d_in[4];
    const float* bn1_m  = (const float*)d_in[5];
    const float* bn1_v  = (const float*)d_in[6];
    const float* w_comb = (const float*)d_in[7];
    const float* b_comb = (const float*)d_in[8];
    const float* bn2_g  = (const float*)d_in[9];
    const float* bn2_b  = (const float*)d_in[10];
    const float* bn2_m  = (const float*)d_in[11];
    const float* bn2_v  = (const float*)d_in[12];

    setup_all<<<dim3(64, 8), 192>>>(w_def, bn1_g, bn1_v, b_def, bn1_b, bn1_m,
                                    w_comb, b_comb, bn2_g, bn2_b, bn2_m, bn2_v);

    cudaFuncSetAttribute(conv_main, cudaFuncAttributeMaxDynamicSharedMemorySize,
                         SMEM_BYTES);
    conv_main<<<dim3(4, 4, 128), 256, SMEM_BYTES>>>(x, (float*)d_out);
}

// round 14
// speedup vs baseline: 1.6286x; 1.0121x over previous
#include <cuda_runtime.h>
#include <cuda_fp16.h>
#include <math.h>

// ---------------- device scratch (static: allocations are forbidden) -------
// Conv A operand, fp16x2 fragment-major for mma.m16n8k16:
// [par(8)][kc(8)][cpi(4)][mt(6)][lane(32)][r(4)]  (each u32 = fp16x2)
__device__ unsigned g_A16[8 * 8 * 3072];
// Combine A operand: [k2(6)][mt(2)][lane(32)][r(4)] fp16x2
__device__ unsigned g_A2[1536];
__device__ float g_bias1[32];
__device__ float g_bias2[32];

// ---------------- helpers ----------------------------------------------------
__device__ __forceinline__ void mma_f16(float* d, const unsigned* a,
                                        unsigned b0, unsigned b1) {
    asm volatile(
        "mma.sync.aligned.m16n8k16.row.col.f32.f16.f16.f32 "
        "{%0,%1,%2,%3}, {%4,%5,%6,%7}, {%8,%9}, {%0,%1,%2,%3};"
        : "+f"(d[0]), "+f"(d[1]), "+f"(d[2]), "+f"(d[3])
        : "r"(a[0]), "r"(a[1]), "r"(a[2]), "r"(a[3]), "r"(b0), "r"(b1));
}
__device__ __forceinline__ void mbar_init(unsigned mbar, unsigned count) {
    asm volatile("mbarrier.init.shared.b64 [%0], %1;" :: "r"(mbar), "r"(count)
                 : "memory");
}
__device__ __forceinline__ void mbar_expect_tx(unsigned mbar, unsigned bytes) {
    asm volatile("mbarrier.arrive.expect_tx.shared.b64 _, [%0], %1;"
                 :: "r"(mbar), "r"(bytes) : "memory");
}
__device__ __forceinline__ void mbar_wait(unsigned mbar, unsigned parity) {
    asm volatile(
        "{\n\t.reg .pred P1;\n\t"
        "WL_%=:\n\t"
        "mbarrier.try_wait.parity.acquire.cta.shared::cta.b64 P1, [%0], %1, 0x989680;\n\t"
        "@P1 bra.uni WD_%=;\n\t"
        "bra.uni WL_%=;\n\t"
        "WD_%=:\n\t}"
        :: "r"(mbar), "r"(parity) : "memory");
}
__device__ __forceinline__ void cp_bulk(unsigned dstS, const void* src,
                                        unsigned bytes, unsigned mbarS) {
    asm volatile(
        "cp.async.bulk.shared::cta.global.mbarrier::complete_tx::bytes "
        "[%0], [%1], %2, [%3];"
        :: "r"(dstS), "l"(src), "r"(bytes), "r"(mbarS) : "memory");
}
__device__ __forceinline__ unsigned smem_u32(const void* p) {
    return (unsigned)(unsigned long long)__cvta_generic_to_shared(p);
}

// per-axis trilinear->original-grid collapse weights (fp32: exact small
// rationals; error ~1e-7 invisible under fp16 quantization)
__device__ __forceinline__ float hvalf(int q, int k, int e, float a) {
    if (q == 0) {
        if (k == 0) return e ? a : (1.0f - a);
        return e ? 1.0f : 0.0f;
    } else {
        if (k == 2) return e ? (1.0f - a) : a;
        return e ? 0.0f : 1.0f;
    }
}

// ---------------- merged setup kernel ----------------------------------------
// grid (64 c, 8 par), block 192 = 6 mt x 32 lanes.
__global__ void setup_all(const float* __restrict__ W,
                          const float* __restrict__ g1, const float* __restrict__ v1,
                          const float* __restrict__ b_def,
                          const float* __restrict__ b1, const float* __restrict__ m1,
                          const float* __restrict__ wcm, const float* __restrict__ bcm,
                          const float* __restrict__ g2, const float* __restrict__ b2,
                          const float* __restrict__ m2, const float* __restrict__ v2) {
    __shared__ float ws[32 * 27];
    int c = blockIdx.x, par = blockIdx.y;
    int tid = threadIdx.x;
    for (int idx = tid; idx < 32 * 27; idx += 192) {
        int co = idx / 27, kk = idx - co * 27;
        ws[idx] = W[co * 1728 + c * 27 + kk];
    }
    __syncthreads();

    int mt = tid >> 5, lane = tid & 31;
    int g = lane >> 2, t4 = lane & 3;
    int qz = (par >> 2) & 1, qy = (par >> 1) & 1, qx = par & 1;

#pragma unroll
    for (int rowbit = 0; rowbit < 2; rowbit++) {
        int m = mt * 16 + g + 8 * rowbit;
        int br = m >> 5, co = m & 31;
        float a = (br == 0) ? 0.0f : (br == 1 ? 0.4f : 0.7f);
        float s1 = g1[co] * rsqrtf(v1[co] + 1e-5f);
        __half hh[2];
#pragma unroll
        for (int h = 0; h < 2; h++) {
            int tap = 2 * t4 + h;
            int ez = (tap >> 2) & 1, ey = (tap >> 1) & 1, ex = tap & 1;
            float hz[3], hy[3], hx[3];
#pragma unroll
            for (int k = 0; k < 3; k++) {
                hz[k] = hvalf(qz, k, ez, a);
                hy[k] = hvalf(qy, k, ey, a);
                hx[k] = hvalf(qx, k, ex, a);
            }
            float sum = 0.f;
#pragma unroll
            for (int kz = 0; kz < 3; kz++)
#pragma unroll
                for (int ky = 0; ky < 3; ky++)
#pragma unroll
                    for (int kx = 0; kx < 3; kx++)
                        sum += ws[co * 27 + kz * 9 + ky * 3 + kx] *
                               (hz[kz] * hy[ky] * hx[kx]);
            hh[h] = __float2half(sum * s1);
        }
        int r = 2 * (c & 1) + rowbit;
        int idx = ((((par * 8 + (c >> 3)) * 4 + ((c >> 1) & 3)) * 6 + mt) * 32 + lane) * 4 + r;
        __half2 hv = __halves2half2(hh[0], hh[1]);
        g_A16[idx] = *(unsigned*)&hv;
    }

    if (blockIdx.x == 0 && blockIdx.y == 0) {
        if (tid < 32) {
            float s1 = g1[tid] * rsqrtf(v1[tid] + 1e-5f);
            g_bias1[tid] = b_def[tid] * s1 + b1[tid] - m1[tid] * s1;
            float s2 = g2[tid] * rsqrtf(v2[tid] + 1e-5f);
            g_bias2[tid] = bcm[tid] * s2 + b2[tid] - m2[tid] * s2;
        }
        for (int idx = tid; idx < 1536; idx += 192) {
            int r = idx & 3, ln = (idx >> 2) & 31, mt2 = (idx >> 7) & 1, k2 = idx >> 8;
            int gg = ln >> 2, tt = ln & 3;
            int m = mt2 * 16 + gg + 8 * (r & 1);
            float s2 = g2[m] * rsqrtf(v2[m] + 1e-5f);
            int ch0 = k2 * 16 + 8 * (r >> 1) + 2 * tt;
            __half2 hv = __halves2half2(__float2half(wcm[m * 96 + ch0] * s2),
                                        __float2half(wcm[m * 96 + ch0 + 1] * s2));
            g_A2[idx] = *(unsigned*)&hv;
        }
    }
}

// ---------------- main fused kernel ------------------------------------------
// block 256 thr = 8 warps; tile = 8(x) x 8(y) x 2(z) orig coords = 128 voxels,
// one parity class; 3 CTAs/SM.
// Warp work split: warp w = (mhalf = w&1) x (ngroup = w>>1):
//   3 M-tiles (48 rows) x 4 N-tiles (32 voxels) -> each A fragment feeds 4 HMMA
//   => A LDS.128 halved vs full-M warps.
// x tile layout: [pos(243)][channel(32, +2 pad)] u32 fp16x2 position-pairs ->
// B fragments (ch c, c+1 at same pos) load as ONE LDS.64.
// A chunks: cp.async.bulk double buffer, leader-wait + syncthreads.
#define XT_STRIDE 34
#define XT_U32 (243 * XT_STRIDE)    // 8262
#define SA2_OFF 8264
#define B1S_OFF 9800
#define B2S_OFF 9832
#define SA_OFF 9864                 // 2 x 3072 u32 A double buffer (16B aligned)
#define MBAR_OFF 16008              // 2 mbarriers (byte 64032, 8-aligned)
#define SMEM_U32 16012
#define SMEM_BYTES (SMEM_U32 * 4)
#define A_CHUNK_BYTES 12288

__global__ void __launch_bounds__(256, 3)
conv_main(const float* __restrict__ x, float* __restrict__ out) {
    extern __shared__ unsigned smu[];
    unsigned* xt = smu;                         // also R_t after conv
    unsigned* sA2 = smu + SA2_OFF;
    float* b1s = (float*)(smu + B1S_OFF);
    float* b2s = (float*)(smu + B2S_OFF);
    unsigned* sA = smu + SA_OFF;

    const unsigned base_u32 = smem_u32(smu);
    const unsigned mbar = base_u32 + MBAR_OFF * 4;
    const unsigned sA_addr = base_u32 + SA_OFF * 4;

    const int tid = threadIdx.x;
    const int w = tid >> 5, lane = tid & 31;
    const int g = lane >> 2, t4 = lane & 3;
    const int mhalf = w & 1, ngrp = w >> 1;

    const int par = blockIdx.z >> 4;
    const int pzt = blockIdx.z & 15;
    const int qz = (par >> 2) & 1, qy = (par >> 1) & 1, qx = par & 1;
    const int Px0 = blockIdx.x * 8, Py0 = blockIdx.y * 8, Pz0 = pzt * 2;
    const int ox = Px0 - 1 + qx, oy = Py0 - 1 + qy, oz = Pz0 - 1 + qz;

    const unsigned* gA = g_A16 + par * 24576;

    // ---- mbarriers + prefetch A chunk 0 ONLY ----
    if (tid == 0) {
        mbar_init(mbar + 0, 1);
        mbar_init(mbar + 8, 1);
    }
    __syncthreads();
    if (tid == 0) {
        mbar_expect_tx(mbar, A_CHUNK_BYTES);
        cp_bulk(sA_addr, gA, A_CHUNK_BYTES, mbar);
    }

    // ---- hoisted loader coords: 1 tile position per thread (243 used) ----
    const int p0 = tid;
    const bool has0 = p0 < 243;
    int z0 = p0 / 81, r0 = p0 - z0 * 81, y0 = r0 / 9, x0 = r0 - y0 * 9;
    int gz0 = oz + z0, gy0 = oy + y0, gx0 = ox + x0;
    const bool ok0 = has0 && ((unsigned)gz0 < 32u) && ((unsigned)gy0 < 32u) &&
                     ((unsigned)gx0 < 32u);
    const int off0 = (gz0 * 32 + gy0) * 32 + gx0;

    // x tile: u32 at [pos][c] = fp16 pair (value at pos, value at pos+1) of ch c.
    auto load_half = [&](int phase) {
        const float* xb = x + phase * 32 * 32768;
        __half* hp = (__half*)xt;
        if (has0) {
#pragma unroll 8
            for (int c = 0; c < 32; c++) {
                float v0 = ok0 ? __ldg(xb + c * 32768 + off0) : 0.f;
                __half h0 = __float2half(v0);
                int i0 = p0 * XT_STRIDE + c;
                hp[2 * i0] = h0;
                if (p0) hp[2 * (i0 - XT_STRIDE) + 1] = h0;
            }
        }
    };

    load_half(0);
    for (int i = tid; i < 1536; i += 256) sA2[i] = g_A2[i];
    if (tid < 32) { b1s[tid] = g_bias1[tid]; b2s[tid] = g_bias2[tid]; }
    __syncthreads();

    // ---- per-lane B gather positions: 4 N-tiles (32 voxels of this ngrp) ----
    int bpos[4];
#pragma unroll
    for (int nt = 0; nt < 4; nt++) {
        int vox = ngrp * 32 + nt * 8 + g;
        bpos[nt] = ((vox >> 6) * 81 + ((vox >> 3) & 7) * 9 + (vox & 7) +
                    (t4 >> 1) * 81 + (t4 & 1) * 9) * XT_STRIDE;
    }

    float d[3][4][4];
#pragma unroll
    for (int i = 0; i < 3; i++)
#pragma unroll
        for (int j = 0; j < 4; j++)
#pragma unroll
            for (int r = 0; r < 4; r++) d[i][j][r] = 0.f;

    // ---- conv GEMM: K = 512 (64 c x 8 taps), 8 chunks of 8 channels ----
#pragma unroll 1
    for (int kc = 0; kc < 8; kc++) {
        if (tid == 0) mbar_wait(mbar + (kc & 1) * 8, (kc >> 1) & 1);
        __syncthreads();   // A[kc] visible; all warps done with buffer (kc+1)&1
        if (tid == 0 && kc < 7) {
            unsigned mb = mbar + ((kc + 1) & 1) * 8;
            mbar_expect_tx(mb, A_CHUNK_BYTES);
            cp_bulk(sA_addr + ((kc + 1) & 1) * A_CHUNK_BYTES,
                    gA + (kc + 1) * 3072, A_CHUNK_BYTES, mb);
        }
        if (kc == 4) {          // phase boundary: channels 32..63
            load_half(1);
            __syncthreads();
        }
        const unsigned* Ab = sA + (kc & 1) * 3072 + (mhalf * 3) * 128 + lane * 4;
        const int cbase = (kc & 3) * 8;

#pragma unroll
        for (int cpi = 0; cpi < 4; cpi++) {
            // B: 4 LDS.64 (single-buffered; latency hides under A LDS.128s)
            uint2 bb[4];
            const int cc = cbase + 2 * cpi;
#pragma unroll
            for (int nt = 0; nt < 4; nt++)
                bb[nt] = *(const uint2*)(xt + bpos[nt] + cc);
#pragma unroll
            for (int mt = 0; mt < 3; mt++) {
                unsigned a[4];
                *(uint4*)a = *(const uint4*)(Ab + (cpi * 6 + mt) * 128);
#pragma unroll
                for (int nt = 0; nt < 4; nt++)
                    mma_f16(d[mt][nt], a, bb[nt].x, bb[nt].y);
            }
        }
    }

    // ---- relu + bias1, stage R_t[vox][96ch] fp16 (stride 100) over xt ----
    __syncthreads();
    {
        __half* Rt = (__half*)xt;
#pragma unroll
        for (int mt = 0; mt < 3; mt++)
#pragma unroll
            for (int nt = 0; nt < 4; nt++)
#pragma unroll
                for (int r = 0; r < 4; r++) {
                    int m = mhalf * 48 + mt * 16 + g + 8 * (r >> 1);
                    int vox = ngrp * 32 + nt * 8 + 2 * t4 + (r & 1);
                    float v = fmaxf(d[mt][nt][r] + b1s[m & 31], 0.f);
                    Rt[vox * 100 + m] = __float2half(v);
                }
    }
    __syncthreads();

    // ---- combine GEMM: D2[32][128] = A2[32][96] * R ----
    float e[2][2][4];
#pragma unroll
    for (int i = 0; i < 2; i++)
#pragma unroll
        for (int j = 0; j < 2; j++)
#pragma unroll
            for (int r = 0; r < 4; r++) e[i][j][r] = 0.f;

#pragma unroll
    for (int k2 = 0; k2 < 6; k2++) {
        unsigned bb0[2], bb1[2];
#pragma unroll
        for (int nt = 0; nt < 2; nt++) {
            int col = w * 16 + nt * 8 + g;
            int base = col * 50 + k2 * 8 + t4;
            bb0[nt] = xt[base];
            bb1[nt] = xt[base + 4];
        }
#pragma unroll
        for (int mt = 0; mt < 2; mt++) {
            unsigned a[4];
            *(uint4*)a = *(const uint4*)(sA2 + (k2 * 2 + mt) * 128 + lane * 4);
#pragma unroll
            for (int nt = 0; nt < 2; nt++)
                mma_f16(e[mt][nt], a, bb0[nt], bb1[nt]);
        }
    }

    // ---- bias2 + relu + store ----
#pragma unroll
    for (int mt = 0; mt < 2; mt++)
#pragma unroll
        for (int nt = 0; nt < 2; nt++)
#pragma unroll
            for (int r = 0; r < 4; r++) {
                int o = mt * 16 + g + 8 * (r >> 1);
                int vox = w * 16 + nt * 8 + 2 * t4 + (r & 1);
                int vx = vox & 7, vy = (vox >> 3) & 7, vz = vox >> 6;
                int gx = 2 * (Px0 + vx) + qx;
                int gy = 2 * (Py0 + vy) + qy;
                int gz = 2 * (Pz0 + vz) + qz;
                out[o * 262144 + gz * 4096 + gy * 64 + gx] =
                    fmaxf(e[mt][nt][r] + b2s[o], 0.f);
            }
}

// ---------------- launch -----------------------------------------------------
extern "C" void kernel_launch(void* const* d_in, const int* in_sizes, int n_in,
                              void* d_out, int out_size) {
    const float* x      = (const float*)d_in[0];
    const float* w_def  = (const float*)d_in[1];
    const float* b_def  = (const float*)d_in[2];
    const float* bn1_g  = (const float*)d_in[3];
    const float* bn1_b  = (const float*)d_in[4];
    const float* bn1_m  = (const float*)d_in[5];
    const float* bn1_v  = (const float*)d_in[6];
    const float* w_comb = (const float*)d_in[7];
    const float* b_comb = (const float*)d_in[8];
    const float* bn2_g  = (const float*)d_in[9];
    const float* bn2_b  = (const float*)d_in[10];
    const float* bn2_m  = (const float*)d_in[11];
    const float* bn2_v  = (const float*)d_in[12];

    setup_all<<<dim3(64, 8), 192>>>(w_def, bn1_g, bn1_v, b_def, bn1_b, bn1_m,
                                    w_comb, b_comb, bn2_g, bn2_b, bn2_m, bn2_v);

    cudaFuncSetAttribute(conv_main, cudaFuncAttributeMaxDynamicSharedMemorySize,
                         SMEM_BYTES);
    conv_main<<<dim3(4, 4, 128), 256, SMEM_BYTES>>>(x, (float*)d_out);
}